// round 1
// baseline (speedup 1.0000x reference)
#include <cuda_runtime.h>
#include <math.h>

// Problem constants
#define BB 2
#define SS 2048
#define HID 2048
#define NH 16
#define NKV 4
#define DH 128
#define REP (NH / NKV)   // 4

// Scratch buffers (device globals; no allocation allowed)
__device__ float g_q[(size_t)BB * SS * NH * DH];    // [b][s][h][d]
__device__ float g_k[(size_t)BB * SS * NKV * DH];   // [b][s][kv][d]
__device__ float g_v[(size_t)BB * SS * NKV * DH];
__device__ float g_o[(size_t)BB * SS * NH * DH];    // attention output, [b][s][h][d]

// ---------------------------------------------------------------------------
// GEMM: C[M,N] = A[M,K] @ W[K,N], all row-major fp32.
// BM=128, BN=64, BK=16, 256 threads, 8x4 per thread.
// ---------------------------------------------------------------------------
__global__ __launch_bounds__(256) void gemm_kernel(
    const float* __restrict__ A, const float* __restrict__ W,
    float* __restrict__ C, int M, int N, int K)
{
    __shared__ float sAt[16][128];   // A tile transposed: [k][m]
    __shared__ float sB[16][64];     // W tile: [k][n]

    const int tid = threadIdx.x;
    const int tx = tid & 15;         // 0..15 (cols)
    const int ty = tid >> 4;         // 0..15 (rows)
    const int m0 = blockIdx.y * 128;
    const int n0 = blockIdx.x * 64;

    float acc[8][4];
#pragma unroll
    for (int r = 0; r < 8; ++r)
#pragma unroll
        for (int c = 0; c < 4; ++c) acc[r][c] = 0.f;

    for (int k0 = 0; k0 < K; k0 += 16) {
        // Load A tile: 128 rows x 16 k -> 512 float4, 2 per thread
#pragma unroll
        for (int i = 0; i < 2; ++i) {
            int f4 = tid + i * 256;
            int row = f4 >> 2;           // 0..127
            int k4 = (f4 & 3) * 4;       // 0,4,8,12
            float4 a = *(const float4*)(A + (size_t)(m0 + row) * K + k0 + k4);
            sAt[k4 + 0][row] = a.x;
            sAt[k4 + 1][row] = a.y;
            sAt[k4 + 2][row] = a.z;
            sAt[k4 + 3][row] = a.w;
        }
        // Load W tile: 16 rows x 64 n -> 256 float4, 1 per thread
        {
            int row = tid >> 4;          // 0..15
            int c4 = (tid & 15) * 4;     // 0..60
            float4 b = *(const float4*)(W + (size_t)(k0 + row) * N + n0 + c4);
            *(float4*)&sB[row][c4] = b;
        }
        __syncthreads();

#pragma unroll
        for (int kk = 0; kk < 16; ++kk) {
            float4 a0 = *(const float4*)&sAt[kk][ty * 8];
            float4 a1 = *(const float4*)&sAt[kk][ty * 8 + 4];
            float4 b  = *(const float4*)&sB[kk][tx * 4];
            float av[8] = {a0.x, a0.y, a0.z, a0.w, a1.x, a1.y, a1.z, a1.w};
            float bv[4] = {b.x, b.y, b.z, b.w};
#pragma unroll
            for (int r = 0; r < 8; ++r)
#pragma unroll
                for (int c = 0; c < 4; ++c)
                    acc[r][c] += av[r] * bv[c];
        }
        __syncthreads();
    }

#pragma unroll
    for (int r = 0; r < 8; ++r) {
        float4 o = make_float4(acc[r][0], acc[r][1], acc[r][2], acc[r][3]);
        *(float4*)(C + (size_t)(m0 + ty * 8 + r) * N + n0 + tx * 4) = o;
    }
}

// ---------------------------------------------------------------------------
// RoPE, in place. One 64-thread block per (b, s, head) row of length D=128.
// out[i]    = x[2i]*cos - x[2i+1]*sin   (i in [0,64))
// out[i+64] = x[2i]*sin + x[2i+1]*cos
// ---------------------------------------------------------------------------
__global__ __launch_bounds__(64) void rope_kernel(float* __restrict__ x, int nheads)
{
    const int row = blockIdx.x;                 // (b*S + s)*nheads + h
    const int s = (row / nheads) % SS;
    float* p = x + (size_t)row * DH;
    const int i = threadIdx.x;                  // 0..63

    float x1 = p[2 * i];
    float x2 = p[2 * i + 1];
    float inv = powf(10000.0f, -(2.0f * i) / 128.0f);
    float f = (float)s * inv;
    float sn, cs;
    sincosf(f, &sn, &cs);
    __syncthreads();   // everyone read before anyone writes (in-place permute)
    p[i]      = x1 * cs - x2 * sn;
    p[i + 64] = x1 * sn + x2 * cs;
}

// ---------------------------------------------------------------------------
// Flash attention with causal mask, online softmax.
// Grid: (S/64 q-tiles, B*H). Block: 256 threads (16x16).
// Dynamic smem: sQT[128][64] | sKT[128][64] | sV[64][128] | sP[64][65]
// ---------------------------------------------------------------------------
#define SM_QT 0
#define SM_KT (128 * 64)
#define SM_V  (2 * 128 * 64)
#define SM_P  (3 * 128 * 64)
#define ATTN_SMEM_FLOATS (3 * 128 * 64 + 64 * 65)
#define ATTN_SMEM_BYTES (ATTN_SMEM_FLOATS * 4)

__global__ __launch_bounds__(256) void attn_kernel(
    const float* __restrict__ Q, const float* __restrict__ K,
    const float* __restrict__ V, float* __restrict__ O)
{
    extern __shared__ float sm[];
    float* sQT = sm + SM_QT;   // [d][row]  stride 64
    float* sKT = sm + SM_KT;   // [d][row]  stride 64
    float* sV  = sm + SM_V;    // [row][d]  stride 128
    float* sP  = sm + SM_P;    // [row][j]  stride 65

    const int tid = threadIdx.x;
    const int tx = tid & 15;
    const int ty = tid >> 4;
    const int qt = blockIdx.x;              // q tile index
    const int bh = blockIdx.y;
    const int b = bh / NH, h = bh % NH;
    const int kvh = h / REP;
    const int q0 = qt * 64;
    const float scale = 0.08838834764831845f; // 1/sqrt(128)

    // Load Q tile (scaled), transposed into smem
#pragma unroll
    for (int i = 0; i < 8; ++i) {
        int f4 = tid + i * 256;             // 0..2047
        int row = f4 >> 5;                  // 0..63
        int c4 = (f4 & 31) * 4;             // 0..124
        float4 qv = *(const float4*)(Q + ((size_t)(b * SS + q0 + row) * NH + h) * DH + c4);
        sQT[(c4 + 0) * 64 + row] = qv.x * scale;
        sQT[(c4 + 1) * 64 + row] = qv.y * scale;
        sQT[(c4 + 2) * 64 + row] = qv.z * scale;
        sQT[(c4 + 3) * 64 + row] = qv.w * scale;
    }

    float m_prev[4], lsum[4], acc[4][8];
#pragma unroll
    for (int r = 0; r < 4; ++r) {
        m_prev[r] = -1e30f;
        lsum[r] = 0.f;
#pragma unroll
        for (int c = 0; c < 8; ++c) acc[r][c] = 0.f;
    }

    for (int t = 0; t <= qt; ++t) {
        const int k0 = t * 64;
        __syncthreads();
        // Load K (transposed) and V tiles
#pragma unroll
        for (int i = 0; i < 8; ++i) {
            int f4 = tid + i * 256;
            int row = f4 >> 5;
            int c4 = (f4 & 31) * 4;
            size_t base = ((size_t)(b * SS + k0 + row) * NKV + kvh) * DH + c4;
            float4 kv = *(const float4*)(K + base);
            sKT[(c4 + 0) * 64 + row] = kv.x;
            sKT[(c4 + 1) * 64 + row] = kv.y;
            sKT[(c4 + 2) * 64 + row] = kv.z;
            sKT[(c4 + 3) * 64 + row] = kv.w;
            float4 vv = *(const float4*)(V + base);
            *(float4*)&sV[row * 128 + c4] = vv;
        }
        __syncthreads();

        // S = (Q*scale) @ K^T : each thread 4x4 (rows ty*4+r, cols tx*4+c)
        float s[4][4];
#pragma unroll
        for (int r = 0; r < 4; ++r)
#pragma unroll
            for (int c = 0; c < 4; ++c) s[r][c] = 0.f;

#pragma unroll 8
        for (int kk = 0; kk < 128; ++kk) {
            float4 a = *(const float4*)&sQT[kk * 64 + ty * 4];
            float4 bk = *(const float4*)&sKT[kk * 64 + tx * 4];
            float av[4] = {a.x, a.y, a.z, a.w};
            float bv[4] = {bk.x, bk.y, bk.z, bk.w};
#pragma unroll
            for (int r = 0; r < 4; ++r)
#pragma unroll
                for (int c = 0; c < 4; ++c)
                    s[r][c] += av[r] * bv[c];
        }

        // Causal mask on the diagonal tile
        if (t == qt) {
#pragma unroll
            for (int r = 0; r < 4; ++r)
#pragma unroll
                for (int c = 0; c < 4; ++c)
                    if (k0 + tx * 4 + c > q0 + ty * 4 + r) s[r][c] = -1e30f;
        }

        // Online softmax (row stats replicated across the 16-lane tx group)
#pragma unroll
        for (int r = 0; r < 4; ++r) {
            float mt = fmaxf(fmaxf(s[r][0], s[r][1]), fmaxf(s[r][2], s[r][3]));
#pragma unroll
            for (int w = 1; w <= 8; w <<= 1)
                mt = fmaxf(mt, __shfl_xor_sync(0xffffffffu, mt, w));
            float m_new = fmaxf(m_prev[r], mt);
            float rescale = __expf(m_prev[r] - m_new);
            float lt = 0.f;
#pragma unroll
            for (int c = 0; c < 4; ++c) {
                float p = __expf(s[r][c] - m_new);
                s[r][c] = p;
                lt += p;
            }
#pragma unroll
            for (int w = 1; w <= 8; w <<= 1)
                lt += __shfl_xor_sync(0xffffffffu, lt, w);
            lsum[r] = lsum[r] * rescale + lt;
            m_prev[r] = m_new;
#pragma unroll
            for (int c = 0; c < 8; ++c) acc[r][c] *= rescale;
            // write P row chunk
#pragma unroll
            for (int c = 0; c < 4; ++c)
                sP[(ty * 4 + r) * 65 + tx * 4 + c] = s[r][c];
        }
        __syncwarp();   // P rows are produced+consumed within the same half-warp group

        // O += P @ V : rows ty*4+r, cols tx*8..tx*8+7
#pragma unroll 4
        for (int j = 0; j < 64; ++j) {
            float p0 = sP[(ty * 4 + 0) * 65 + j];
            float p1 = sP[(ty * 4 + 1) * 65 + j];
            float p2 = sP[(ty * 4 + 2) * 65 + j];
            float p3 = sP[(ty * 4 + 3) * 65 + j];
            float4 v0 = *(const float4*)&sV[j * 128 + tx * 8];
            float4 v1 = *(const float4*)&sV[j * 128 + tx * 8 + 4];
            float vv[8] = {v0.x, v0.y, v0.z, v0.w, v1.x, v1.y, v1.z, v1.w};
            float pv[4] = {p0, p1, p2, p3};
#pragma unroll
            for (int r = 0; r < 4; ++r)
#pragma unroll
                for (int c = 0; c < 8; ++c)
                    acc[r][c] += pv[r] * vv[c];
        }
    }

    // Normalize and write out: [b][q][h][d]
#pragma unroll
    for (int r = 0; r < 4; ++r) {
        float inv_l = 1.0f / lsum[r];
        float4 o0 = make_float4(acc[r][0] * inv_l, acc[r][1] * inv_l,
                                acc[r][2] * inv_l, acc[r][3] * inv_l);
        float4 o1 = make_float4(acc[r][4] * inv_l, acc[r][5] * inv_l,
                                acc[r][6] * inv_l, acc[r][7] * inv_l);
        size_t base = ((size_t)(b * SS + q0 + ty * 4 + r) * NH + h) * DH + tx * 8;
        *(float4*)(O + base) = o0;
        *(float4*)(O + base + 4) = o1;
    }
}

// ---------------------------------------------------------------------------
// Launch
// ---------------------------------------------------------------------------
extern "C" void kernel_launch(void* const* d_in, const int* in_sizes, int n_in,
                              void* d_out, int out_size)
{
    const float* x  = (const float*)d_in[0];
    // d_in[1] = mask (causal tril, known statically — unused)
    const float* Wq = (const float*)d_in[2];
    const float* Wk = (const float*)d_in[3];
    const float* Wv = (const float*)d_in[4];
    const float* Wo = (const float*)d_in[5];
    float* out = (float*)d_out;

    float *q, *k, *v, *o;
    cudaGetSymbolAddress((void**)&q, g_q);
    cudaGetSymbolAddress((void**)&k, g_k);
    cudaGetSymbolAddress((void**)&v, g_v);
    cudaGetSymbolAddress((void**)&o, g_o);

    const int M = BB * SS;   // 4096

    // Projections
    gemm_kernel<<<dim3((NH * DH) / 64, M / 128), 256>>>(x, Wq, q, M, NH * DH, HID);
    gemm_kernel<<<dim3((NKV * DH) / 64, M / 128), 256>>>(x, Wk, k, M, NKV * DH, HID);
    gemm_kernel<<<dim3((NKV * DH) / 64, M / 128), 256>>>(x, Wv, v, M, NKV * DH, HID);

    // RoPE (in place)
    rope_kernel<<<BB * SS * NH, 64>>>(q, NH);
    rope_kernel<<<BB * SS * NKV, 64>>>(k, NKV);

    // Flash attention
    cudaFuncSetAttribute(attn_kernel, cudaFuncAttributeMaxDynamicSharedMemorySize,
                         ATTN_SMEM_BYTES);
    attn_kernel<<<dim3(SS / 64, BB * NH), 256, ATTN_SMEM_BYTES>>>(q, k, v, o);

    // Output projection
    gemm_kernel<<<dim3(HID / 64, M / 128), 256>>>(o, Wo, out, M, HID, HID * 0 + NH * DH);
}

// round 2
// speedup vs baseline: 3.0455x; 3.0455x over previous
#include <cuda_runtime.h>
#include <math.h>

// Problem constants
#define BB 2
#define SS 2048
#define HID 2048
#define NH 16
#define NKV 4
#define DH 128
#define REP (NH / NKV)   // 4

// Scratch buffers
__device__ float g_q[(size_t)BB * SS * NH * DH];    // [b][s][h][d]
__device__ float g_k[(size_t)BB * SS * NKV * DH];
__device__ float g_v[(size_t)BB * SS * NKV * DH];
__device__ float g_o[(size_t)BB * SS * NH * DH];

__device__ __forceinline__ unsigned f2tf(float f) {
    unsigned u;
    asm("cvt.rna.tf32.f32 %0, %1;" : "=r"(u) : "f"(f));
    return u;
}

#define MMA_TF32(c, a, b) \
    asm volatile( \
        "mma.sync.aligned.m16n8k8.row.col.f32.tf32.tf32.f32 " \
        "{%0,%1,%2,%3}, {%4,%5,%6,%7}, {%8,%9}, {%0,%1,%2,%3};\n" \
        : "+f"((c)[0]), "+f"((c)[1]), "+f"((c)[2]), "+f"((c)[3]) \
        : "r"((a)[0]), "r"((a)[1]), "r"((a)[2]), "r"((a)[3]), \
          "r"((b)[0]), "r"((b)[1]))

// ---------------------------------------------------------------------------
// TF32 tensor-core GEMM: C[M,N] = A[M,K] @ W[K,N], row-major fp32.
// Block 256 thr (8 warps), BM=128 BN=128 BK=32, warp tile 32x64.
// ---------------------------------------------------------------------------
__global__ __launch_bounds__(256) void gemm_tc(
    const float* __restrict__ A, const float* __restrict__ W,
    float* __restrict__ C, int M, int N, int K)
{
    __shared__ unsigned sA[128][36];   // [m][k], +4 pad -> bank = 4g+ct
    __shared__ unsigned sB[32][132];   // [k][n], +4 pad -> bank = 4ct+g

    const int tid = threadIdx.x;
    const int warp = tid >> 5, lane = tid & 31;
    const int g = lane >> 2, ct = lane & 3;
    const int wm = warp >> 1, wn = warp & 1;
    const int m0 = blockIdx.y * 128, n0 = blockIdx.x * 128;

    float c[2][8][4];
#pragma unroll
    for (int mt = 0; mt < 2; ++mt)
#pragma unroll
        for (int nt = 0; nt < 8; ++nt)
#pragma unroll
            for (int i = 0; i < 4; ++i) c[mt][nt][i] = 0.f;

    // staging indices
    const int ar0 = tid >> 3;            // A: f4 = tid + i*256, rows f4>>3
    const int ac = (tid & 7) * 4;
    const int br0 = tid >> 5;            // B: rows f4>>5
    const int bc = (tid & 31) * 4;

    float4 ra[4], rb[4];

    // initial load (k0 = 0)
#pragma unroll
    for (int i = 0; i < 4; ++i) {
        ra[i] = *(const float4*)(A + (size_t)(m0 + ar0 + i * 32) * K + ac);
        rb[i] = *(const float4*)(W + (size_t)(br0 + i * 8) * N + n0 + bc);
    }

    const int niter = K / 32;
    for (int it = 0; it < niter; ++it) {
        // store staged tile to smem (with tf32 convert)
#pragma unroll
        for (int i = 0; i < 4; ++i) {
            *(uint4*)&sA[ar0 + i * 32][ac] =
                make_uint4(f2tf(ra[i].x), f2tf(ra[i].y), f2tf(ra[i].z), f2tf(ra[i].w));
            *(uint4*)&sB[br0 + i * 8][bc] =
                make_uint4(f2tf(rb[i].x), f2tf(rb[i].y), f2tf(rb[i].z), f2tf(rb[i].w));
        }
        __syncthreads();

        if (it + 1 < niter) {
            int k0 = (it + 1) * 32;
#pragma unroll
            for (int i = 0; i < 4; ++i) {
                ra[i] = *(const float4*)(A + (size_t)(m0 + ar0 + i * 32) * K + k0 + ac);
                rb[i] = *(const float4*)(W + (size_t)(k0 + br0 + i * 8) * N + n0 + bc);
            }
        }

#pragma unroll
        for (int ks = 0; ks < 4; ++ks) {
            const int kk = ks * 8;
            unsigned a[2][4], b[8][2];
#pragma unroll
            for (int mt = 0; mt < 2; ++mt) {
                int r = wm * 32 + mt * 16;
                a[mt][0] = sA[r + g][kk + ct];
                a[mt][1] = sA[r + g + 8][kk + ct];
                a[mt][2] = sA[r + g][kk + ct + 4];
                a[mt][3] = sA[r + g + 8][kk + ct + 4];
            }
#pragma unroll
            for (int nt = 0; nt < 8; ++nt) {
                int cb = wn * 64 + nt * 8;
                b[nt][0] = sB[kk + ct][cb + g];
                b[nt][1] = sB[kk + ct + 4][cb + g];
            }
#pragma unroll
            for (int mt = 0; mt < 2; ++mt)
#pragma unroll
                for (int nt = 0; nt < 8; ++nt)
                    MMA_TF32(c[mt][nt], a[mt], b[nt]);
        }
        __syncthreads();
    }

#pragma unroll
    for (int mt = 0; mt < 2; ++mt)
#pragma unroll
        for (int nt = 0; nt < 8; ++nt) {
            int row = m0 + wm * 32 + mt * 16 + g;
            int col = n0 + wn * 64 + nt * 8 + 2 * ct;
            *(float2*)(C + (size_t)row * N + col) =
                make_float2(c[mt][nt][0], c[mt][nt][1]);
            *(float2*)(C + (size_t)(row + 8) * N + col) =
                make_float2(c[mt][nt][2], c[mt][nt][3]);
        }
}

// ---------------------------------------------------------------------------
// RoPE, in place.
// ---------------------------------------------------------------------------
__global__ __launch_bounds__(64) void rope_kernel(float* __restrict__ x, int nheads)
{
    const int row = blockIdx.x;
    const int s = (row / nheads) % SS;
    float* p = x + (size_t)row * DH;
    const int i = threadIdx.x;

    float x1 = p[2 * i];
    float x2 = p[2 * i + 1];
    float inv = powf(10000.0f, -(2.0f * i) / 128.0f);
    float f = (float)s * inv;
    float sn, cs;
    sincosf(f, &sn, &cs);
    __syncthreads();
    p[i]      = x1 * cs - x2 * sn;
    p[i + 64] = x1 * sn + x2 * cs;
}

// ---------------------------------------------------------------------------
// Flash attention, TF32 tensor cores.
// Block: 256 thr (8 warps), 128 q-rows/block (16 per warp), 64-key tiles.
// Smem (uint words): sQ[128][132] | sK[64][132] | sV[64][132] | sP[128][68]
// ---------------------------------------------------------------------------
#define SQ_O 0
#define SK_O (128 * 132)
#define SV_O (128 * 132 + 64 * 132)
#define SP_O (128 * 132 + 2 * 64 * 132)
#define ATTN_SMEM_WORDS (128 * 132 + 2 * 64 * 132 + 128 * 68)
#define ATTN_SMEM_BYTES (ATTN_SMEM_WORDS * 4)

__global__ __launch_bounds__(256) void attn_tc(
    const float* __restrict__ Q, const float* __restrict__ K,
    const float* __restrict__ V, float* __restrict__ O)
{
    extern __shared__ unsigned smu[];
    unsigned* sQ = smu + SQ_O;   // [row][d] stride 132
    unsigned* sK = smu + SK_O;   // [key][d] stride 132
    unsigned* sV = smu + SV_O;   // [key][d] stride 132
    unsigned* sP = smu + SP_O;   // [row][key] stride 68

    const int tid = threadIdx.x;
    const int warp = tid >> 5, lane = tid & 31;
    const int g = lane >> 2, ct = lane & 3;
    const int bh = blockIdx.y;
    const int b = bh / NH, h = bh % NH;
    const int kvh = h / REP;
    const int q0 = blockIdx.x * 128;
    const float scale = 0.08838834764831845f;

    // Load Q tile (pre-scaled)
#pragma unroll
    for (int i = 0; i < 16; ++i) {
        int f4 = tid + i * 256;
        int row = f4 >> 5;
        int c4 = (f4 & 31) * 4;
        float4 qv = *(const float4*)(Q + ((size_t)(b * SS + q0 + row) * NH + h) * DH + c4);
        *(uint4*)&sQ[row * 132 + c4] = make_uint4(
            f2tf(qv.x * scale), f2tf(qv.y * scale),
            f2tf(qv.z * scale), f2tf(qv.w * scale));
    }

    float m_prev[2] = {-1e30f, -1e30f};
    float lsum[2] = {0.f, 0.f};
    float o[16][4];
#pragma unroll
    for (int nt = 0; nt < 16; ++nt)
#pragma unroll
        for (int i = 0; i < 4; ++i) o[nt][i] = 0.f;

    const int rbase = 16 * warp;               // warp's q-row base in tile
    const int tmax = (q0 + 128) / 64;

    for (int t = 0; t < tmax; ++t) {
        const int k0g = t * 64;
        __syncthreads();
        // Load K and V tiles
#pragma unroll
        for (int i = 0; i < 8; ++i) {
            int f4 = tid + i * 256;
            int row = f4 >> 5;
            int c4 = (f4 & 31) * 4;
            size_t base = ((size_t)(b * SS + k0g + row) * NKV + kvh) * DH + c4;
            float4 kv = *(const float4*)(K + base);
            *(uint4*)&sK[row * 132 + c4] =
                make_uint4(f2tf(kv.x), f2tf(kv.y), f2tf(kv.z), f2tf(kv.w));
            float4 vv = *(const float4*)(V + base);
            *(uint4*)&sV[row * 132 + c4] =
                make_uint4(f2tf(vv.x), f2tf(vv.y), f2tf(vv.z), f2tf(vv.w));
        }
        __syncthreads();

        // S = Q @ K^T  (warp: 16 rows x 64 keys, 8 n-tiles)
        float s[8][4];
#pragma unroll
        for (int nt = 0; nt < 8; ++nt)
#pragma unroll
            for (int i = 0; i < 4; ++i) s[nt][i] = 0.f;

#pragma unroll
        for (int ks = 0; ks < 16; ++ks) {
            const int kk = ks * 8;
            unsigned a[4], bfr[8][2];
            a[0] = sQ[(rbase + g) * 132 + kk + ct];
            a[1] = sQ[(rbase + g + 8) * 132 + kk + ct];
            a[2] = sQ[(rbase + g) * 132 + kk + ct + 4];
            a[3] = sQ[(rbase + g + 8) * 132 + kk + ct + 4];
#pragma unroll
            for (int nt = 0; nt < 8; ++nt) {
                bfr[nt][0] = sK[(nt * 8 + g) * 132 + kk + ct];
                bfr[nt][1] = sK[(nt * 8 + g) * 132 + kk + ct + 4];
            }
#pragma unroll
            for (int nt = 0; nt < 8; ++nt)
                MMA_TF32(s[nt], a, bfr[nt]);
        }

        // Causal mask (only needed near the diagonal)
        if (k0g + 63 > q0 + rbase) {
            int row0 = q0 + rbase + g;
#pragma unroll
            for (int nt = 0; nt < 8; ++nt) {
                int col = k0g + nt * 8 + 2 * ct;
                if (col > row0)         s[nt][0] = -1e30f;
                if (col + 1 > row0)     s[nt][1] = -1e30f;
                if (col > row0 + 8)     s[nt][2] = -1e30f;
                if (col + 1 > row0 + 8) s[nt][3] = -1e30f;
            }
        }

        // Online softmax for the two rows this thread touches (g, g+8)
        float resc[2];
#pragma unroll
        for (int r = 0; r < 2; ++r) {
            float mt = -1e30f;
#pragma unroll
            for (int nt = 0; nt < 8; ++nt)
                mt = fmaxf(mt, fmaxf(s[nt][2 * r], s[nt][2 * r + 1]));
            mt = fmaxf(mt, __shfl_xor_sync(0xffffffffu, mt, 1));
            mt = fmaxf(mt, __shfl_xor_sync(0xffffffffu, mt, 2));
            float m_new = fmaxf(m_prev[r], mt);
            resc[r] = __expf(m_prev[r] - m_new);
            float lt = 0.f;
#pragma unroll
            for (int nt = 0; nt < 8; ++nt) {
                float p0 = __expf(s[nt][2 * r] - m_new);
                float p1 = __expf(s[nt][2 * r + 1] - m_new);
                s[nt][2 * r] = p0;
                s[nt][2 * r + 1] = p1;
                lt += p0 + p1;
            }
            lt += __shfl_xor_sync(0xffffffffu, lt, 1);
            lt += __shfl_xor_sync(0xffffffffu, lt, 2);
            lsum[r] = lsum[r] * resc[r] + lt;
            m_prev[r] = m_new;
        }
        // rescale accumulators
#pragma unroll
        for (int nt = 0; nt < 16; ++nt) {
            o[nt][0] *= resc[0];
            o[nt][1] *= resc[0];
            o[nt][2] *= resc[1];
            o[nt][3] *= resc[1];
        }
        // write P to smem (tf32)
#pragma unroll
        for (int nt = 0; nt < 8; ++nt) {
            *(uint2*)&sP[(rbase + g) * 68 + nt * 8 + 2 * ct] =
                make_uint2(f2tf(s[nt][0]), f2tf(s[nt][1]));
            *(uint2*)&sP[(rbase + g + 8) * 68 + nt * 8 + 2 * ct] =
                make_uint2(f2tf(s[nt][2]), f2tf(s[nt][3]));
        }
        __syncwarp();

        // O += P @ V  (16 rows x 128 d, 16 n-tiles, K-dim 64)
#pragma unroll
        for (int ks = 0; ks < 8; ++ks) {
            const int kk = ks * 8;
            unsigned a[4];
            a[0] = sP[(rbase + g) * 68 + kk + ct];
            a[1] = sP[(rbase + g + 8) * 68 + kk + ct];
            a[2] = sP[(rbase + g) * 68 + kk + ct + 4];
            a[3] = sP[(rbase + g + 8) * 68 + kk + ct + 4];
#pragma unroll
            for (int nt = 0; nt < 16; ++nt) {
                unsigned bfr[2];
                bfr[0] = sV[(kk + ct) * 132 + nt * 8 + g];
                bfr[1] = sV[(kk + ct + 4) * 132 + nt * 8 + g];
                MMA_TF32(o[nt], a, bfr);
            }
        }
        __syncwarp();
    }

    // Epilogue: normalize and write O [b][s][h][d]
    float inv0 = 1.0f / lsum[0];
    float inv1 = 1.0f / lsum[1];
    int row0 = q0 + rbase + g;
#pragma unroll
    for (int nt = 0; nt < 16; ++nt) {
        int col = nt * 8 + 2 * ct;
        size_t b0a = ((size_t)(b * SS + row0) * NH + h) * DH + col;
        size_t b1a = ((size_t)(b * SS + row0 + 8) * NH + h) * DH + col;
        *(float2*)(O + b0a) = make_float2(o[nt][0] * inv0, o[nt][1] * inv0);
        *(float2*)(O + b1a) = make_float2(o[nt][2] * inv1, o[nt][3] * inv1);
    }
}

// ---------------------------------------------------------------------------
// Launch
// ---------------------------------------------------------------------------
extern "C" void kernel_launch(void* const* d_in, const int* in_sizes, int n_in,
                              void* d_out, int out_size)
{
    const float* x  = (const float*)d_in[0];
    const float* Wq = (const float*)d_in[2];
    const float* Wk = (const float*)d_in[3];
    const float* Wv = (const float*)d_in[4];
    const float* Wo = (const float*)d_in[5];
    float* out = (float*)d_out;

    float *q, *k, *v, *o;
    cudaGetSymbolAddress((void**)&q, g_q);
    cudaGetSymbolAddress((void**)&k, g_k);
    cudaGetSymbolAddress((void**)&v, g_v);
    cudaGetSymbolAddress((void**)&o, g_o);

    const int M = BB * SS;   // 4096

    // Projections (TF32 tensor cores)
    gemm_tc<<<dim3((NH * DH) / 128, M / 128), 256>>>(x, Wq, q, M, NH * DH, HID);
    gemm_tc<<<dim3((NKV * DH) / 128, M / 128), 256>>>(x, Wk, k, M, NKV * DH, HID);
    gemm_tc<<<dim3((NKV * DH) / 128, M / 128), 256>>>(x, Wv, v, M, NKV * DH, HID);

    // RoPE (in place)
    rope_kernel<<<BB * SS * NH, 64>>>(q, NH);
    rope_kernel<<<BB * SS * NKV, 64>>>(k, NKV);

    // Flash attention (TF32 tensor cores)
    cudaFuncSetAttribute(attn_tc, cudaFuncAttributeMaxDynamicSharedMemorySize,
                         ATTN_SMEM_BYTES);
    attn_tc<<<dim3(SS / 128, BB * NH), 256, ATTN_SMEM_BYTES>>>(q, k, v, o);

    // Output projection
    gemm_tc<<<dim3(HID / 128, M / 128), 256>>>(o, Wo, out, M, HID, NH * DH);
}